// round 8
// baseline (speedup 1.0000x reference)
#include <cuda_runtime.h>
#include <cuda_fp16.h>
#include <cstdint>
#include <cstddef>

// ============================================================================
// WaveletBasis: out[B,O] = haar_basis(x).coeffs + x @ base_weight ; kl = 0
//   B=32768, F=1024, O=64, NB=8
// One fp16 GEMM (fp32 accum), mma.sync HMMA (tcgen05 rejected: harness ptxas
// targets sm_103 without the 'a' feature set):
//   out = A[B,8192] * Bm[8192,64] + bias
// Per feature f (8 K-slots), j = clip(floor(8u),0,7), u=(tanh x+1)/2:
//   A slots = [x, s0, s1, s0s1, s2, s1s2, s0s2, s0s1s2]  (signs from bits of j)
//   Bm rows = [bw, c1, R(c2+c3), R(c2-c3), H4-rotated c4..c7 / 2], R=sqrt2/2
//   bias[o] = sum_f coeffs[f,o,0]
// j computed WITHOUT tanh: u >= i/8  <=>  x >= atanh(i/4 - 1).
// Pipeline: 3-stage smem ring, 1 barrier/iter; x reg-prefetch depth 2;
// B via cp.async.cg; B fragments via ldmatrix x4 (16-row pairs).
// ============================================================================

static constexpr int FDIM   = 1024;
static constexpr int NCHUNK = 128;            // K chunks of 64 (8 features)
static constexpr int OUT_ELEMS = 32768 * 64;

#define T1 (-0.9729550745276566f)
#define T2 (-0.5493061443340548f)
#define T3 (-0.2554128118829953f)
#define T5 ( 0.2554128118829953f)
#define T6 ( 0.5493061443340548f)
#define T7 ( 0.9729550745276566f)

// B operand fp16, linear chunk layout: [kt=128][n=64][kp=8] uint4 = 1 MB
__device__ uint4 g_B4[NCHUNK * 512];
__device__ float g_bias[64];

// smem ring (dynamic): padded rows, 144 B stride (72 halves)
static constexpr int A_STG = 128 * 144;                 // 18432
static constexpr int B_STG = 64 * 144;                  // 9216
static constexpr int SM_A  = 0;
static constexpr int SM_B  = 3 * A_STG;                 // 55296
static constexpr int SMEM_TOTAL = SM_B + 3 * B_STG;     // 82944

// ---- PTX helpers -----------------------------------------------------------
#define LDMX4(R, ADDR)                                                           \
    asm volatile("ldmatrix.sync.aligned.m8n8.x4.shared.b16 {%0,%1,%2,%3}, [%4];" \
                 : "=r"((R)[0]), "=r"((R)[1]), "=r"((R)[2]), "=r"((R)[3])        \
                 : "r"(ADDR))
#define MMA16816(C, A, B0, B1)                                                   \
    asm volatile("mma.sync.aligned.m16n8k16.row.col.f32.f16.f16.f32 "            \
                 "{%0,%1,%2,%3}, {%4,%5,%6,%7}, {%8,%9}, {%0,%1,%2,%3};"         \
                 : "+f"((C)[0]), "+f"((C)[1]), "+f"((C)[2]), "+f"((C)[3])        \
                 : "r"((A)[0]), "r"((A)[1]), "r"((A)[2]), "r"((A)[3]),           \
                   "r"(B0), "r"(B1))
#define CP_ASYNC16(DST, SRC)                                                     \
    asm volatile("cp.async.cg.shared.global [%0], [%1], 16;"                     \
                 :: "r"(DST), "l"(SRC) : "memory")
#define CP_COMMIT()  asm volatile("cp.async.commit_group;" ::: "memory")
#define CP_WAIT1()   asm volatile("cp.async.wait_group 1;" ::: "memory")
#define STS128(r0, r1, r2, r3, addr)                                             \
    asm volatile("st.shared.v4.b32 [%0], {%1, %2, %3, %4};"                      \
                 :: "r"(addr), "r"(r0), "r"(r1), "r"(r2), "r"(r3) : "memory")

// ---------------------------------------------------------------------------
// Prologue 1: rotated B (fp16), linear chunk layout
// ---------------------------------------------------------------------------
__global__ void wb_prep_B(const float* __restrict__ coeffs,
                          const float* __restrict__ bw) {
    int gid = blockIdx.x * blockDim.x + threadIdx.x;   // 65536 = F*O
    int f = gid >> 6;
    int o = gid & 63;
    const float* c = coeffs + (size_t)(f * 64 + o) * 8;
    float c1 = c[1], c2 = c[2], c3 = c[3];
    float c4 = c[4], c5 = c[5], c6 = c[6], c7 = c[7];
    float w = bw[f * 64 + o];
    const float R = 0.70710678118654752f;
    float v[8];
    v[0] = w;
    v[1] = c1;
    v[2] = R * (c2 + c3);
    v[3] = R * (c2 - c3);
    v[4] = 0.5f * (c4 + c5 + c6 + c7);
    v[5] = 0.5f * (c4 - c5 + c6 - c7);
    v[6] = 0.5f * (c4 + c5 - c6 - c7);
    v[7] = 0.5f * (c4 - c5 - c6 + c7);
    unsigned p[4];
#pragma unroll
    for (int i = 0; i < 4; i++) {
        unsigned lo = (unsigned)__half_as_ushort(__float2half(v[2 * i]));
        unsigned hi = (unsigned)__half_as_ushort(__float2half(v[2 * i + 1]));
        p[i] = lo | (hi << 16);
    }
    uint4 pk; pk.x = p[0]; pk.y = p[1]; pk.z = p[2]; pk.w = p[3];
    int kt = f >> 3, fl = f & 7;
    g_B4[kt * 512 + o * 8 + fl] = pk;
}

// ---------------------------------------------------------------------------
// Prologue 2: bias[o] = sum_f coeffs[f,o,0]
// ---------------------------------------------------------------------------
__global__ void wb_prep_bias(const float* __restrict__ coeffs) {
    __shared__ float red[128];
    int o = blockIdx.x;
    int t = threadIdx.x;
    float s = 0.f;
    for (int f = t; f < FDIM; f += 128)
        s += coeffs[(size_t)(f * 64 + o) * 8];
    red[t] = s;
    __syncthreads();
#pragma unroll
    for (int st = 64; st > 0; st >>= 1) {
        if (t < st) red[t] += red[t + st];
        __syncthreads();
    }
    if (t == 0) g_bias[o] = red[0];
}

// ---------------------------------------------------------------------------
// Main GEMM: 256 CTAs x 128 threads. CTA tile M=128, N=64, K streamed.
// ---------------------------------------------------------------------------
__device__ __forceinline__ void gen_A(uint32_t a_sts, const float4& lo,
                                      const float4& hi) {
    float xa[8] = {lo.x, lo.y, lo.z, lo.w, hi.x, hi.y, hi.z, hi.w};
#pragma unroll
    for (int i = 0; i < 8; i++) {
        float xs = xa[i];
        bool b2 = xs >= 0.0f;
        bool b1 = xs >= (b2 ? T6 : T2);
        bool b0 = xs >= (b2 ? (b1 ? T7 : T5) : (b1 ? T3 : T1));
        unsigned s0 = b2 ? 0x8000u : 0u;
        unsigned s1 = b1 ? 0x8000u : 0u;
        unsigned s2 = b0 ? 0x8000u : 0u;
        const unsigned ONE = 0x3C00u;
        unsigned hx = (unsigned)__half_as_ushort(__float2half(xs));
        unsigned q0 = hx | ((ONE | s0) << 16);
        unsigned q1 = (ONE | s1) | ((ONE | (s0 ^ s1)) << 16);
        unsigned q2 = (ONE | s2) | ((ONE | (s1 ^ s2)) << 16);
        unsigned q3 = (ONE | (s0 ^ s2)) | ((ONE | (s0 ^ s1 ^ s2)) << 16);
        STS128(q0, q1, q2, q3, a_sts + i * 16);
    }
}

__global__ void __launch_bounds__(128, 2)
wb_main(const float* __restrict__ x, float* __restrict__ out, int out_size) {
    extern __shared__ __align__(128) char smem[];
    const uint32_t sb = (uint32_t)__cvta_generic_to_shared(smem);
    const int t = threadIdx.x;
    const int w = t >> 5;
    const int l = t & 31;
    const int bx = blockIdx.x;

    float acc[2][8][4];
#pragma unroll
    for (int g = 0; g < 2; g++)
#pragma unroll
        for (int nb = 0; nb < 8; nb++)
#pragma unroll
            for (int i = 0; i < 4; i++) acc[g][nb][i] = 0.f;

    // producer addressing: thread t owns row t of the A tile (8 features/chunk)
    const float* px = x + (size_t)(bx * 128 + t) * FDIM;
    const uint32_t a_sts = sb + SM_A + (uint32_t)t * 144u;

    // cp.async B: 4 x 16B per thread, id = t + j*128 -> (n = id>>3, kp = id&7)
    uint32_t b_dst[4];
    const uint4* b_src_base = g_B4;
#pragma unroll
    for (int j = 0; j < 4; j++) {
        int id = t + j * 128;
        b_dst[j] = sb + SM_B + (uint32_t)((id >> 3) * 144 + (id & 7) * 16);
    }

    // consumer addressing (byte offsets within a stage)
    const uint32_t a_off0 = (uint32_t)((w * 32 + (l & 15)) * 144 + (l >> 4) * 16);
    const uint32_t a_off1 = a_off0 + 16 * 144;
    uint32_t b_off[4];
#pragma unroll
    for (int p = 0; p < 4; p++)
        b_off[p] = (uint32_t)((p * 16 + ((l >> 4) << 3) + (l & 7)) * 144 +
                              ((l >> 3) & 1) * 16);

    // ---- prologue: B(0) in flight, A(0) generated, x(1),x(2) prefetched ----
#pragma unroll
    for (int j = 0; j < 4; j++)
        CP_ASYNC16(b_dst[j], (const void*)(b_src_base + 0 * 512 + t + j * 128));
    CP_COMMIT();

    {
        float4 x0a = *(const float4*)(px + 0);
        float4 x0b = *(const float4*)(px + 4);
        gen_A(a_sts, x0a, x0b);
    }
    float4 xpa[2], xpb[2];
    xpa[1] = *(const float4*)(px + 1 * 8);     // for gen(1) at iter 0
    xpb[1] = *(const float4*)(px + 1 * 8 + 4);
    xpa[0] = *(const float4*)(px + 2 * 8);     // for gen(2) at iter 1
    xpb[0] = *(const float4*)(px + 2 * 8 + 4);

    // ---- main loop: 1 barrier / iter, 3-stage ring ----
#pragma unroll 1
    for (int kt = 0; kt < NCHUNK; kt++) {
        const int sc = kt % 3;              // compute stage
        const int sg = (kt + 1) % 3;        // gen stage

        // produce chunk kt+1 (stage sg was last read at compute(kt-2))
        if (kt + 1 < NCHUNK) {
#pragma unroll
            for (int j = 0; j < 4; j++)
                CP_ASYNC16(b_dst[j] + (uint32_t)(sg * B_STG),
                           (const void*)(b_src_base + (kt + 1) * 512 + t + j * 128));
            const int slot = (kt + 1) & 1;
            gen_A(a_sts + (uint32_t)(sg * A_STG), xpa[slot], xpb[slot]);
            if (kt + 3 < NCHUNK) {
                xpa[slot] = *(const float4*)(px + (kt + 3) * 8);
                xpb[slot] = *(const float4*)(px + (kt + 3) * 8 + 4);
            }
        }
        CP_COMMIT();
        CP_WAIT1();              // B(kt) resident (own parts)
        __syncthreads();         // everyone's A(kt) STS + B(kt) parts visible

        // ---- compute chunk kt ----
        const uint32_t ab = sb + SM_A + (uint32_t)(sc * A_STG);
        const uint32_t bb = sb + SM_B + (uint32_t)(sc * B_STG);
#pragma unroll
        for (int ks = 0; ks < 4; ks++) {
            const uint32_t ko = (uint32_t)(ks * 32);
            uint32_t a0[4], a1[4], bf[4][4];
            LDMX4(a0, ab + a_off0 + ko);
            LDMX4(a1, ab + a_off1 + ko);
#pragma unroll
            for (int p = 0; p < 4; p++) LDMX4(bf[p], bb + b_off[p] + ko);
#pragma unroll
            for (int p = 0; p < 4; p++) {
                MMA16816(acc[0][2 * p],     a0, bf[p][0], bf[p][1]);
                MMA16816(acc[1][2 * p],     a1, bf[p][0], bf[p][1]);
                MMA16816(acc[0][2 * p + 1], a0, bf[p][2], bf[p][3]);
                MMA16816(acc[1][2 * p + 1], a1, bf[p][2], bf[p][3]);
            }
        }
    }

    // ---- epilogue: add bias, store fp32 ----
    const int col0 = (l & 3) * 2;
    float2 bias2[8];
#pragma unroll
    for (int nb = 0; nb < 8; nb++)
        bias2[nb] = *(const float2*)&g_bias[nb * 8 + col0];

#pragma unroll
    for (int g = 0; g < 2; g++) {
        int row0 = bx * 128 + w * 32 + g * 16 + (l >> 2);
#pragma unroll
        for (int nb = 0; nb < 8; nb++) {
            float2 v0, v1;
            v0.x = acc[g][nb][0] + bias2[nb].x;
            v0.y = acc[g][nb][1] + bias2[nb].y;
            v1.x = acc[g][nb][2] + bias2[nb].x;
            v1.y = acc[g][nb][3] + bias2[nb].y;
            *(float2*)(out + (size_t)row0 * 64 + nb * 8 + col0) = v0;
            *(float2*)(out + (size_t)(row0 + 8) * 64 + nb * 8 + col0) = v1;
        }
    }

    // kl output (zeros) — tail elements past the [B,O] block
    if (bx == 0 && t == 0) {
        for (int i = OUT_ELEMS; i < out_size; i++) out[i] = 0.f;
    }
}

// ---------------------------------------------------------------------------
extern "C" void kernel_launch(void* const* d_in, const int* in_sizes, int n_in,
                              void* d_out, int out_size) {
    const float* x      = (const float*)d_in[0];   // [32768,1024] f32
    const float* coeffs = (const float*)d_in[1];   // [1024,64,8]  f32
    const float* bw     = (const float*)d_in[2];   // [1024,64]    f32
    float* out = (float*)d_out;

    cudaFuncSetAttribute(wb_main, cudaFuncAttributeMaxDynamicSharedMemorySize,
                         SMEM_TOTAL);

    wb_prep_B<<<512, 128>>>(coeffs, bw);
    wb_prep_bias<<<64, 128>>>(coeffs);
    wb_main<<<256, 128, SMEM_TOTAL>>>(x, out, out_size);
}